// round 1
// baseline (speedup 1.0000x reference)
#include <cuda_runtime.h>
#include <math_constants.h>

#define NN 20000
#define HIDDEN 128
#define HEADS 8
#define LAP 16
#define NBUCKETS 1024
#define NBINS 32
#define MAXDEG 64
#define NE 320000
#define DIN (HIDDEN + LAP)

// ---------------- device scratch (no allocations allowed) ----------------
__device__ float g_hidden_q[NN * HIDDEN];
__device__ float g_hidden_k[NN * HIDDEN];
__device__ float g_hbuf[NN * HIDDEN];
__device__ int g_bq[NN];
__device__ int g_bk[NN];
__device__ int g_bcnt[NBUCKETS];
__device__ int g_bstart[NBUCKETS + 1];
__device__ int g_bcur[NBUCKETS];
__device__ int g_bnodes[NN];
__device__ int g_scnt[NN];
__device__ int g_soff[NN + 1];
__device__ int g_scur[NN];
__device__ int g_extra[NN];
__device__ int g_edst[NE];

// ---------------- generic tiled SGEMM: C = act(A@B + bias) ----------------
// A: M x K row-major (if concat: A is M x HIDDEN, A2 is M x LAP, K = HIDDEN+LAP)
// B: K x Nn row-major.  C: M x Nn row-major.  Nn % 64 == 0, K % 16 == 0.
__global__ void sgemm_kernel(const float* __restrict__ A, const float* __restrict__ A2,
                             const float* __restrict__ B, const float* __restrict__ bias,
                             float* __restrict__ C, int M, int Nn, int K,
                             int relu, int concat)
{
    const int BM = 64, BN = 64, BK = 16;
    __shared__ float As[BK][BM + 4];
    __shared__ float Bs[BK][BN];
    int t = threadIdx.x;
    int bm = blockIdx.y * BM, bn = blockIdx.x * BN;
    int ty = t >> 4, tx = t & 15;
    int ar = t >> 2, ak = (t & 3) * 4;   // A tile: row ar (0..63), k chunk ak
    int bkr = t >> 4, bn0 = (t & 15) * 4; // B tile: k row bkr (0..15), n chunk bn0
    float acc[4][4] = {};

    for (int kt = 0; kt < K; kt += BK) {
        // load A tile (64 x 16)
        int row = bm + ar;
        float4 av = make_float4(0.f, 0.f, 0.f, 0.f);
        if (row < M) {
            int k0 = kt + ak;
            if (!concat) {
                av = *(const float4*)(A + (size_t)row * K + k0);
            } else if (k0 < HIDDEN) {
                av = *(const float4*)(A + (size_t)row * HIDDEN + k0);
            } else {
                av = *(const float4*)(A2 + (size_t)row * LAP + (k0 - HIDDEN));
            }
        }
        As[ak + 0][ar] = av.x;
        As[ak + 1][ar] = av.y;
        As[ak + 2][ar] = av.z;
        As[ak + 3][ar] = av.w;
        // load B tile (16 x 64)
        *(float4*)&Bs[bkr][bn0] = *(const float4*)(B + (size_t)(kt + bkr) * Nn + bn + bn0);
        __syncthreads();
#pragma unroll
        for (int kk = 0; kk < BK; kk++) {
            float4 a4 = *(const float4*)&As[kk][ty * 4];
            float4 b4 = *(const float4*)&Bs[kk][tx * 4];
            float aa[4] = {a4.x, a4.y, a4.z, a4.w};
            float bb[4] = {b4.x, b4.y, b4.z, b4.w};
#pragma unroll
            for (int i2 = 0; i2 < 4; i2++)
#pragma unroll
                for (int j2 = 0; j2 < 4; j2++)
                    acc[i2][j2] += aa[i2] * bb[j2];
        }
        __syncthreads();
    }
#pragma unroll
    for (int i2 = 0; i2 < 4; i2++) {
        int gm = bm + ty * 4 + i2;
        if (gm >= M) continue;
#pragma unroll
        for (int j2 = 0; j2 < 4; j2++) {
            int gn = bn + tx * 4 + j2;
            float v = acc[i2][j2] + bias[gn];
            if (relu) v = fmaxf(v, 0.f);
            C[(size_t)gm * Nn + gn] = v;
        }
    }
}

// ---------------- argmax over 1024 buckets, one warp per row ----------------
__global__ void argmax_kernel(const float* __restrict__ L, int* __restrict__ outb)
{
    int w = (blockIdx.x * blockDim.x + threadIdx.x) >> 5;
    int lane = threadIdx.x & 31;
    if (w >= NN) return;
    const float* row = L + (size_t)w * NBUCKETS;
    float best = -CUDART_INF_F;
    int bidx = 0;
#pragma unroll 4
    for (int t2 = 0; t2 < NBUCKETS / 32; t2++) {
        int idx = t2 * 32 + lane;
        float v = row[idx];
        if (v > best) { best = v; bidx = idx; }  // ascending idx -> strict '>' keeps first
    }
    for (int o = 16; o; o >>= 1) {
        float v2 = __shfl_xor_sync(~0u, best, o);
        int i2 = __shfl_xor_sync(~0u, bidx, o);
        if (v2 > best || (v2 == best && i2 < bidx)) { best = v2; bidx = i2; }
    }
    if (lane == 0) outb[w] = bidx;
}

// ---------------- counting sort of K-nodes by bucket, edge CSR ----------------
__global__ void zero_kernel()
{
    int i = blockIdx.x * blockDim.x + threadIdx.x;
    if (i < NBUCKETS) { g_bcnt[i] = 0; g_bcur[i] = 0; }
    if (i < NN) { g_scnt[i] = 0; g_scur[i] = 0; }
}

__global__ void count_bk_kernel()
{
    int i = blockIdx.x * blockDim.x + threadIdx.x;
    if (i < NN) atomicAdd(&g_bcnt[g_bk[i]], 1);
}

__global__ void count_src_kernel(const int* __restrict__ ei)
{
    int e = blockIdx.x * blockDim.x + threadIdx.x;
    if (e < NE) atomicAdd(&g_scnt[ei[e]], 1);
}

__global__ void scan1024_kernel()  // exclusive scan of g_bcnt -> g_bstart
{
    __shared__ int sh[NBUCKETS];
    int t = threadIdx.x;
    sh[t] = g_bcnt[t];
    __syncthreads();
    for (int o = 1; o < NBUCKETS; o <<= 1) {
        int x = (t >= o) ? sh[t - o] : 0;
        __syncthreads();
        sh[t] += x;
        __syncthreads();
    }
    g_bstart[t + 1] = sh[t];
    if (t == 0) g_bstart[0] = 0;
}

__global__ void scanN_kernel()  // exclusive scan of g_scnt -> g_soff (single block)
{
    __shared__ int sh[1024];
    __shared__ int carry;
    int t = threadIdx.x;
    if (t == 0) { carry = 0; g_soff[0] = 0; }
    __syncthreads();
    for (int base = 0; base < NN; base += 1024) {
        int v = (base + t < NN) ? g_scnt[base + t] : 0;
        sh[t] = v;
        __syncthreads();
        for (int o = 1; o < 1024; o <<= 1) {
            int x = (t >= o) ? sh[t - o] : 0;
            __syncthreads();
            sh[t] += x;
            __syncthreads();
        }
        if (base + t < NN) g_soff[base + t + 1] = carry + sh[t];
        __syncthreads();
        if (t == 0) carry += sh[1023];
        __syncthreads();
    }
}

__global__ void scatter_bk_kernel()
{
    int i = blockIdx.x * blockDim.x + threadIdx.x;
    if (i >= NN) return;
    int b = g_bk[i];
    int p = g_bstart[b] + atomicAdd(&g_bcur[b], 1);
    g_bnodes[p] = i;
}

__global__ void scatter_edge_kernel(const int* __restrict__ ei)
{
    int e = blockIdx.x * blockDim.x + threadIdx.x;
    if (e >= NE) return;
    int s = ei[e];
    int p = g_soff[s] + atomicAdd(&g_scur[s], 1);
    g_edst[p] = ei[NE + e];
}

// sort each src's dst list, drop duplicates and pairs already covered by the
// LSH set {j : bk[j]==bq[s], j!=s}; keep self-loops (LSH excludes i==j).
__global__ void sortfilter_kernel()
{
    int s = blockIdx.x * blockDim.x + threadIdx.x;
    if (s >= NN) return;
    int off = g_soff[s], cnt = g_soff[s + 1] - off;
    for (int a = 1; a < cnt; a++) {   // insertion sort (avg ~16 entries)
        int key = g_edst[off + a];
        int b = a - 1;
        while (b >= 0 && g_edst[off + b] > key) {
            g_edst[off + b + 1] = g_edst[off + b];
            b--;
        }
        g_edst[off + b + 1] = key;
    }
    int myb = g_bq[s];
    int m2 = 0, prev = -1;
    for (int a = 0; a < cnt; a++) {
        int j = g_edst[off + a];
        if (j == prev) continue;
        prev = j;
        if (j != s && g_bk[j] == myb) continue;  // already in LSH set
        g_edst[off + m2++] = j;
    }
    g_extra[s] = m2;
}

// ---------------- attention: one warp per src, online segment softmax ----------------
__global__ void attn_kernel(const float* __restrict__ Q, const float* __restrict__ K,
                            const float* __restrict__ V, const float* __restrict__ lap,
                            const float* __restrict__ spd_bias,
                            const float* __restrict__ dse_emb,
                            const float* __restrict__ dde_emb,
                            const float* __restrict__ bnds,
                            const int* __restrict__ deg)
{
    int w = (blockIdx.x * blockDim.x + threadIdx.x) >> 5;
    int lane = threadIdx.x & 31;
    if (w >= NN) return;
    int i = w;
    float4 q4 = *(const float4*)(Q + (size_t)i * HIDDEN + lane * 4);
    float pei = lap[i * LAP + (lane & 15)];
    float bnd = bnds[lane];                 // NBINS == 32, one per lane
    int h = lane >> 2;                      // head owned by this 4-lane group
    int dsrc = min(max(deg[i], 0), MAXDEG + 1);
    float dse_h = dse_emb[dsrc * HEADS + h];

    float m = -CUDART_INF_F, dden = 0.f;
    float4 acc = make_float4(0.f, 0.f, 0.f, 0.f);

    int b = g_bq[i];
    int p0 = g_bstart[b], nlsh = g_bstart[b + 1] - p0;
    int eo = g_soff[i], ec = g_extra[i];
    int total = nlsh + ec;

    for (int p = 0; p < total; p++) {
        int j;
        if (p < nlsh) {
            j = g_bnodes[p0 + p];
            if (j == i) continue;           // warp-uniform
        } else {
            j = g_edst[eo + (p - nlsh)];
        }
        // per-head QK dot: lanes 4h..4h+3 cover dims 16h..16h+16
        float4 k4 = *(const float4*)(K + (size_t)j * HIDDEN + lane * 4);
        float s = q4.x * k4.x + q4.y * k4.y + q4.z * k4.z + q4.w * k4.w;
        s += __shfl_xor_sync(~0u, s, 1);
        s += __shfl_xor_sync(~0u, s, 2);
        // pe distance: both half-warps compute dims 0..15 -> identical sums
        float pj = lap[j * LAP + (lane & 15)];
        float dd = pei - pj;
        float d2 = dd * dd;
        d2 += __shfl_xor_sync(~0u, d2, 1);
        d2 += __shfl_xor_sync(~0u, d2, 2);
        d2 += __shfl_xor_sync(~0u, d2, 4);
        d2 += __shfl_xor_sync(~0u, d2, 8);
        float dist = sqrtf(d2);
        // searchsorted(boundaries, dist, 'left') == #{boundaries < dist}
        unsigned bal = __ballot_sync(~0u, bnd < dist);
        int idx = __popc(bal);
        int dj = min(max(deg[j], 0), MAXDEG + 1);
        float sc = s * 0.25f + spd_bias[idx * HEADS + h] + dse_h + dde_emb[dj * HEADS + h];
        // online softmax (identical across the 4 lanes of a head group)
        if (sc > m) {
            float f = __expf(m - sc);
            dden *= f;
            acc.x *= f; acc.y *= f; acc.z *= f; acc.w *= f;
            m = sc;
        }
        float wgt = __expf(sc - m);
        dden += wgt;
        float4 v4 = *(const float4*)(V + (size_t)j * HIDDEN + lane * 4);
        acc.x += wgt * v4.x; acc.y += wgt * v4.y;
        acc.z += wgt * v4.z; acc.w += wgt * v4.w;
    }
    float inv = 1.f / (dden + 1e-16f);
    float4 o = make_float4(acc.x * inv, acc.y * inv, acc.z * inv, acc.w * inv);
    *(float4*)(g_hbuf + (size_t)i * HIDDEN + lane * 4) = o;
}

// ---------------- launch ----------------
extern "C" void kernel_launch(void* const* d_in, const int* in_sizes, int n_in,
                              void* d_out, int out_size)
{
    const float* Q    = (const float*)d_in[0];
    const float* Kin  = (const float*)d_in[1];
    const float* V    = (const float*)d_in[2];
    const float* lap  = (const float*)d_in[3];
    const float* Wq1  = (const float*)d_in[4];
    const float* bq1  = (const float*)d_in[5];
    const float* Wq2  = (const float*)d_in[6];
    const float* bq2  = (const float*)d_in[7];
    const float* Wk1  = (const float*)d_in[8];
    const float* bk1  = (const float*)d_in[9];
    const float* Wk2  = (const float*)d_in[10];
    const float* bk2  = (const float*)d_in[11];
    const float* spdb = (const float*)d_in[12];
    const float* dse  = (const float*)d_in[13];
    const float* dde  = (const float*)d_in[14];
    const float* Wout = (const float*)d_in[15];
    const float* bout = (const float*)d_in[16];
    const float* bnds = (const float*)d_in[17];
    const int*   ei   = (const int*)d_in[18];
    const int*   deg  = (const int*)d_in[19];

    float* out = (float*)d_out;
    float* l_q = out + (size_t)NN * HIDDEN;
    float* l_k = l_q + (size_t)NN * NBUCKETS;

    float *hq, *hk, *hb;
    int *pbq, *pbk;
    cudaGetSymbolAddress((void**)&hq, g_hidden_q);
    cudaGetSymbolAddress((void**)&hk, g_hidden_k);
    cudaGetSymbolAddress((void**)&hb, g_hbuf);
    cudaGetSymbolAddress((void**)&pbq, g_bq);
    cudaGetSymbolAddress((void**)&pbk, g_bk);

    zero_kernel<<<(NN + 255) / 256, 256>>>();

    dim3 g1(HIDDEN / 64, (NN + 63) / 64);
    sgemm_kernel<<<g1, 256>>>(Q,   lap, Wq1, bq1, hq, NN, HIDDEN, DIN, 1, 1);
    sgemm_kernel<<<g1, 256>>>(Kin, lap, Wk1, bk1, hk, NN, HIDDEN, DIN, 1, 1);

    dim3 g2(NBUCKETS / 64, (NN + 63) / 64);
    sgemm_kernel<<<g2, 256>>>(hq, nullptr, Wq2, bq2, l_q, NN, NBUCKETS, HIDDEN, 0, 0);
    sgemm_kernel<<<g2, 256>>>(hk, nullptr, Wk2, bk2, l_k, NN, NBUCKETS, HIDDEN, 0, 0);

    int warp_grid = (NN * 32 + 255) / 256;
    argmax_kernel<<<warp_grid, 256>>>(l_q, pbq);
    argmax_kernel<<<warp_grid, 256>>>(l_k, pbk);

    count_bk_kernel<<<(NN + 255) / 256, 256>>>();
    count_src_kernel<<<(NE + 255) / 256, 256>>>(ei);
    scan1024_kernel<<<1, NBUCKETS>>>();
    scanN_kernel<<<1, 1024>>>();
    scatter_bk_kernel<<<(NN + 255) / 256, 256>>>();
    scatter_edge_kernel<<<(NE + 255) / 256, 256>>>(ei);
    sortfilter_kernel<<<(NN + 255) / 256, 256>>>();

    attn_kernel<<<warp_grid, 256>>>(Q, Kin, V, lap, spdb, dse, dde, bnds, deg);

    dim3 g3(HIDDEN / 64, (NN + 63) / 64);
    sgemm_kernel<<<g3, 256>>>(hb, nullptr, Wout, bout, out, NN, HIDDEN, HIDDEN, 0, 0);
}

// round 2
// speedup vs baseline: 1.5709x; 1.5709x over previous
#include <cuda_runtime.h>
#include <math_constants.h>

#define NN 20000
#define HIDDEN 128
#define HEADS 8
#define LAP 16
#define NBUCKETS 1024
#define NBINS 32
#define MAXDEG 64
#define NE 320000
#define DIN (HIDDEN + LAP)
#define TQ 16
#define TK 32
#define MAXT 4096

// ---------------- device scratch (no allocations allowed) ----------------
__device__ float g_hidden_q[NN * HIDDEN];
__device__ float g_hidden_k[NN * HIDDEN];
__device__ float g_hbuf[NN * HIDDEN];
__device__ int g_bq[NN];
__device__ int g_bk[NN];
__device__ int g_bcnt[NBUCKETS];
__device__ int g_bstart[NBUCKETS + 1];
__device__ int g_bcur[NBUCKETS];
__device__ int g_bnodes[NN];
__device__ int g_qcnt[NBUCKETS];
__device__ int g_qstart[NBUCKETS + 1];
__device__ int g_qcur[NBUCKETS];
__device__ int g_qnodes[NN];
__device__ int g_scnt[NN];
__device__ int g_soff[NN + 1];
__device__ int g_scur[NN];
__device__ int g_extra[NN];
__device__ int g_edst[NE];
__device__ int g_tile_b[MAXT];
__device__ int g_tile_off[MAXT];
__device__ int g_ntiles;

// ---------------- tiled SGEMM 128x128x8, 8x8 register tile ----------------
// C = act(A@B + bias). A: MxK row-major (concat: A is MxHIDDEN, A2 MxLAP).
// Requires Nn % 128 == 0, K % 8 == 0 (144, 128 both OK).
__global__ __launch_bounds__(256) void sgemm_kernel(
    const float* __restrict__ A, const float* __restrict__ A2,
    const float* __restrict__ B, const float* __restrict__ bias,
    float* __restrict__ C, int M, int Nn, int K, int relu, int concat)
{
    const int BM = 128, BN = 128, BK = 8;
    __shared__ float As[BK][BM + 4];  // pad to 132 (16B-aligned rows)
    __shared__ float Bs[BK][BN];
    int t = threadIdx.x;
    int bm = blockIdx.y * BM, bn = blockIdx.x * BN;
    int tx = t & 15, ty = t >> 4;
    int arow = t >> 1, ak = (t & 1) * 4;    // A: 128 rows x 8 k, one float4/thread
    int bkr = t >> 5, bcol = (t & 31) * 4;  // B: 8 k x 128 cols
    float acc[8][8] = {};

    for (int kt = 0; kt < K; kt += BK) {
        int row = bm + arow;
        float4 av = make_float4(0.f, 0.f, 0.f, 0.f);
        if (row < M) {
            int k0 = kt + ak;
            if (!concat) {
                av = *(const float4*)(A + (size_t)row * K + k0);
            } else if (k0 < HIDDEN) {
                av = *(const float4*)(A + (size_t)row * HIDDEN + k0);
            } else {
                av = *(const float4*)(A2 + (size_t)row * LAP + (k0 - HIDDEN));
            }
        }
        As[ak + 0][arow] = av.x;
        As[ak + 1][arow] = av.y;
        As[ak + 2][arow] = av.z;
        As[ak + 3][arow] = av.w;
        *(float4*)&Bs[bkr][bcol] = *(const float4*)(B + (size_t)(kt + bkr) * Nn + bn + bcol);
        __syncthreads();
#pragma unroll
        for (int kk = 0; kk < BK; kk++) {
            float a[8], b[8];
            *(float4*)(a)     = *(const float4*)&As[kk][ty * 8];
            *(float4*)(a + 4) = *(const float4*)&As[kk][ty * 8 + 4];
            *(float4*)(b)     = *(const float4*)&Bs[kk][tx * 8];
            *(float4*)(b + 4) = *(const float4*)&Bs[kk][tx * 8 + 4];
#pragma unroll
            for (int i2 = 0; i2 < 8; i2++)
#pragma unroll
                for (int j2 = 0; j2 < 8; j2++)
                    acc[i2][j2] += a[i2] * b[j2];
        }
        __syncthreads();
    }
#pragma unroll
    for (int i2 = 0; i2 < 8; i2++) {
        int gm = bm + ty * 8 + i2;
        if (gm >= M) continue;
#pragma unroll
        for (int j2 = 0; j2 < 8; j2++) {
            int gn = bn + tx * 8 + j2;
            float v = acc[i2][j2] + bias[gn];
            if (relu) v = fmaxf(v, 0.f);
            C[(size_t)gm * Nn + gn] = v;
        }
    }
}

// ---------------- argmax over 1024 buckets, one warp per row ----------------
__global__ void argmax_kernel(const float* __restrict__ L, int* __restrict__ outb)
{
    int w = (blockIdx.x * blockDim.x + threadIdx.x) >> 5;
    int lane = threadIdx.x & 31;
    if (w >= NN) return;
    const float* row = L + (size_t)w * NBUCKETS;
    float best = -CUDART_INF_F;
    int bidx = 0;
#pragma unroll 4
    for (int t2 = 0; t2 < NBUCKETS / 32; t2++) {
        int idx = t2 * 32 + lane;
        float v = row[idx];
        if (v > best) { best = v; bidx = idx; }
    }
    for (int o = 16; o; o >>= 1) {
        float v2 = __shfl_xor_sync(~0u, best, o);
        int i2 = __shfl_xor_sync(~0u, bidx, o);
        if (v2 > best || (v2 == best && i2 < bidx)) { best = v2; bidx = i2; }
    }
    if (lane == 0) outb[w] = bidx;
}

// ---------------- bucket grouping / edge CSR ----------------
__global__ void zero_kernel()
{
    int i = blockIdx.x * blockDim.x + threadIdx.x;
    if (i < NBUCKETS) { g_bcnt[i] = 0; g_bcur[i] = 0; g_qcnt[i] = 0; g_qcur[i] = 0; }
    if (i < NN) { g_scnt[i] = 0; g_scur[i] = 0; }
    if (i == 0) g_ntiles = 0;
}

__global__ void count_kernel(const int* __restrict__ ei)
{
    int i = blockIdx.x * blockDim.x + threadIdx.x;
    if (i < NN) {
        atomicAdd(&g_bcnt[g_bk[i]], 1);
        atomicAdd(&g_qcnt[g_bq[i]], 1);
    }
    if (i < NE) atomicAdd(&g_scnt[ei[i]], 1);
}

__global__ void scan1024_kernel(const int* __restrict__ cnt, int* __restrict__ start)
{
    __shared__ int sh[NBUCKETS];
    int t = threadIdx.x;
    sh[t] = cnt[t];
    __syncthreads();
    for (int o = 1; o < NBUCKETS; o <<= 1) {
        int x = (t >= o) ? sh[t - o] : 0;
        __syncthreads();
        sh[t] += x;
        __syncthreads();
    }
    start[t + 1] = sh[t];
    if (t == 0) start[0] = 0;
}

__global__ void scanN_kernel()
{
    __shared__ int sh[1024];
    __shared__ int carry;
    int t = threadIdx.x;
    if (t == 0) { carry = 0; g_soff[0] = 0; }
    __syncthreads();
    for (int base = 0; base < NN; base += 1024) {
        int v = (base + t < NN) ? g_scnt[base + t] : 0;
        sh[t] = v;
        __syncthreads();
        for (int o = 1; o < 1024; o <<= 1) {
            int x = (t >= o) ? sh[t - o] : 0;
            __syncthreads();
            sh[t] += x;
            __syncthreads();
        }
        if (base + t < NN) g_soff[base + t + 1] = carry + sh[t];
        __syncthreads();
        if (t == 0) carry += sh[1023];
        __syncthreads();
    }
}

__global__ void scatter_kernel(const int* __restrict__ ei)
{
    int i = blockIdx.x * blockDim.x + threadIdx.x;
    if (i < NN) {
        int b = g_bk[i];
        int p = g_bstart[b] + atomicAdd(&g_bcur[b], 1);
        g_bnodes[p] = i;
        int qb = g_bq[i];
        int q = g_qstart[qb] + atomicAdd(&g_qcur[qb], 1);
        g_qnodes[q] = i;
    }
    if (i < NE) {
        int s = ei[i];
        int p = g_soff[s] + atomicAdd(&g_scur[s], 1);
        g_edst[p] = ei[NE + i];
    }
}

__global__ void build_tiles_kernel()
{
    int b = blockIdx.x * blockDim.x + threadIdx.x;
    if (b >= NBUCKETS) return;
    int nq = g_qstart[b + 1] - g_qstart[b];
    if (nq == 0) return;
    int nt = (nq + TQ - 1) / TQ;
    int pos = atomicAdd(&g_ntiles, nt);
    for (int k = 0; k < nt; k++) {
        g_tile_b[pos + k] = b;
        g_tile_off[pos + k] = k * TQ;
    }
}

// sort each src's dst list, drop duplicates and pairs already covered by the
// LSH set {j : bk[j]==bq[s], j!=s}; keep self-loops (LSH excludes i==j).
__global__ void sortfilter_kernel()
{
    int s = blockIdx.x * blockDim.x + threadIdx.x;
    if (s >= NN) return;
    int off = g_soff[s], cnt = g_soff[s + 1] - off;
    for (int a = 1; a < cnt; a++) {
        int key = g_edst[off + a];
        int b = a - 1;
        while (b >= 0 && g_edst[off + b] > key) {
            g_edst[off + b + 1] = g_edst[off + b];
            b--;
        }
        g_edst[off + b + 1] = key;
    }
    int myb = g_bq[s];
    int m2 = 0, prev = -1;
    for (int a = 0; a < cnt; a++) {
        int j = g_edst[off + a];
        if (j == prev) continue;
        prev = j;
        if (j != s && g_bk[j] == myb) continue;
        g_edst[off + m2++] = j;
    }
    g_extra[s] = m2;
}

// ---------------- bucket-dense attention, smem K/V tiles ----------------
// One block = TQ srcs of one bucket (one warp per src). Loops over the
// bucket's K-node list in TK tiles staged in shared memory.
__global__ __launch_bounds__(512) void attn_dense_kernel(
    const float* __restrict__ Q, const float* __restrict__ K,
    const float* __restrict__ V, const float* __restrict__ lap,
    const float* __restrict__ spd_bias,
    const float* __restrict__ dse_emb,
    const float* __restrict__ dde_emb,
    const float* __restrict__ bnds,
    const int* __restrict__ deg)
{
    __shared__ float4 Ks4[TK][32];
    __shared__ float4 Vs4[TK][32];
    __shared__ float laps_s[TK][16];
    __shared__ float dde_s[TK * HEADS];
    __shared__ float spd_s[(NBINS + 1) * HEADS];
    __shared__ int jid[TK];

    int t = blockIdx.x;
    if (t >= g_ntiles) return;
    int tid = threadIdx.x;
    int w = tid >> 5, lane = tid & 31;

    if (tid < (NBINS + 1) * HEADS) spd_s[tid] = spd_bias[tid];

    int b = g_tile_b[t], qo = g_tile_off[t];
    int q0 = g_qstart[b], nq = g_qstart[b + 1] - q0;
    int valid = (qo + w) < nq;
    int i = valid ? g_qnodes[q0 + qo + w] : 0;

    float4 q4 = *(const float4*)(Q + (size_t)i * HIDDEN + lane * 4);
    float pei = lap[i * LAP + (lane & 15)];
    float bnd = bnds[lane];
    int h = lane >> 2;
    int dsrc = min(max(deg[i], 0), MAXDEG + 1);
    float dse_h = dse_emb[dsrc * HEADS + h];

    float m = -CUDART_INF_F, dden = 0.f;
    float4 acc = make_float4(0.f, 0.f, 0.f, 0.f);

    int p0 = g_bstart[b], nk = g_bstart[b + 1] - p0;

    for (int kt = 0; kt < nk; kt += TK) {
        int cnt = min(TK, nk - kt);
        __syncthreads();   // protect previous iteration's smem reads
        if (tid < cnt) jid[tid] = g_bnodes[p0 + kt + tid];
        if (tid < cnt * HEADS) {
            int jj = tid >> 3;
            int j = g_bnodes[p0 + kt + jj];
            int dj = min(max(deg[j], 0), MAXDEG + 1);
            dde_s[tid] = dde_emb[dj * HEADS + (tid & 7)];
        }
        if (tid < cnt * LAP) {
            int jj = tid >> 4;
            int j = g_bnodes[p0 + kt + jj];
            laps_s[jj][tid & 15] = lap[j * LAP + (tid & 15)];
        }
        for (int x = tid; x < cnt * 32; x += 512) {
            int jj = x >> 5, l = x & 31;
            int j = g_bnodes[p0 + kt + jj];
            Ks4[jj][l] = ((const float4*)(K + (size_t)j * HIDDEN))[l];
            Vs4[jj][l] = ((const float4*)(V + (size_t)j * HIDDEN))[l];
        }
        __syncthreads();
        if (valid) {
            for (int jj = 0; jj < cnt; jj++) {
                int j = jid[jj];
                if (j == i) continue;   // warp-uniform
                float4 k4 = Ks4[jj][lane];
                float s = q4.x * k4.x + q4.y * k4.y + q4.z * k4.z + q4.w * k4.w;
                s += __shfl_xor_sync(~0u, s, 1);
                s += __shfl_xor_sync(~0u, s, 2);
                float dd = pei - laps_s[jj][lane & 15];
                float d2 = dd * dd;
                d2 += __shfl_xor_sync(~0u, d2, 1);
                d2 += __shfl_xor_sync(~0u, d2, 2);
                d2 += __shfl_xor_sync(~0u, d2, 4);
                d2 += __shfl_xor_sync(~0u, d2, 8);
                float dist = sqrtf(d2);
                unsigned bal = __ballot_sync(~0u, bnd < dist);
                int idx = __popc(bal);
                float sc = s * 0.25f + spd_s[idx * HEADS + h] + dse_h + dde_s[jj * HEADS + h];
                if (sc > m) {
                    float f = __expf(m - sc);
                    dden *= f;
                    acc.x *= f; acc.y *= f; acc.z *= f; acc.w *= f;
                    m = sc;
                }
                float wgt = __expf(sc - m);
                dden += wgt;
                float4 v4 = Vs4[jj][lane];
                acc.x += wgt * v4.x; acc.y += wgt * v4.y;
                acc.z += wgt * v4.z; acc.w += wgt * v4.w;
            }
        }
    }
    __syncthreads();   // spd_s safety when nk == 0

    if (valid) {
        // graph-edge extras (deduped, LSH-filtered) — global loads, few per src
        int eo = g_soff[i], ec = g_extra[i];
        for (int e = 0; e < ec; e++) {
            int j = g_edst[eo + e];
            float4 k4 = *(const float4*)(K + (size_t)j * HIDDEN + lane * 4);
            float s = q4.x * k4.x + q4.y * k4.y + q4.z * k4.z + q4.w * k4.w;
            s += __shfl_xor_sync(~0u, s, 1);
            s += __shfl_xor_sync(~0u, s, 2);
            float dd = pei - lap[j * LAP + (lane & 15)];
            float d2 = dd * dd;
            d2 += __shfl_xor_sync(~0u, d2, 1);
            d2 += __shfl_xor_sync(~0u, d2, 2);
            d2 += __shfl_xor_sync(~0u, d2, 4);
            d2 += __shfl_xor_sync(~0u, d2, 8);
            float dist = sqrtf(d2);
            unsigned bal = __ballot_sync(~0u, bnd < dist);
            int idx = __popc(bal);
            int dj = min(max(deg[j], 0), MAXDEG + 1);
            float sc = s * 0.25f + spd_s[idx * HEADS + h] + dse_h + dde_emb[dj * HEADS + h];
            if (sc > m) {
                float f = __expf(m - sc);
                dden *= f;
                acc.x *= f; acc.y *= f; acc.z *= f; acc.w *= f;
                m = sc;
            }
            float wgt = __expf(sc - m);
            dden += wgt;
            float4 v4 = *(const float4*)(V + (size_t)j * HIDDEN + lane * 4);
            acc.x += wgt * v4.x; acc.y += wgt * v4.y;
            acc.z += wgt * v4.z; acc.w += wgt * v4.w;
        }
        float inv = 1.f / (dden + 1e-16f);
        float4 o = make_float4(acc.x * inv, acc.y * inv, acc.z * inv, acc.w * inv);
        *(float4*)(g_hbuf + (size_t)i * HIDDEN + lane * 4) = o;
    }
}

// ---------------- launch ----------------
extern "C" void kernel_launch(void* const* d_in, const int* in_sizes, int n_in,
                              void* d_out, int out_size)
{
    const float* Q    = (const float*)d_in[0];
    const float* Kin  = (const float*)d_in[1];
    const float* V    = (const float*)d_in[2];
    const float* lap  = (const float*)d_in[3];
    const float* Wq1  = (const float*)d_in[4];
    const float* bq1  = (const float*)d_in[5];
    const float* Wq2  = (const float*)d_in[6];
    const float* bq2  = (const float*)d_in[7];
    const float* Wk1  = (const float*)d_in[8];
    const float* bk1  = (const float*)d_in[9];
    const float* Wk2  = (const float*)d_in[10];
    const float* bk2  = (const float*)d_in[11];
    const float* spdb = (const float*)d_in[12];
    const float* dse  = (const float*)d_in[13];
    const float* dde  = (const float*)d_in[14];
    const float* Wout = (const float*)d_in[15];
    const float* bout = (const float*)d_in[16];
    const float* bnds = (const float*)d_in[17];
    const int*   ei   = (const int*)d_in[18];
    const int*   deg  = (const int*)d_in[19];

    float* out = (float*)d_out;
    float* l_q = out + (size_t)NN * HIDDEN;
    float* l_k = l_q + (size_t)NN * NBUCKETS;

    float *hq, *hk, *hb;
    int *pbq, *pbk, *pbcnt, *pbstart, *pqcnt, *pqstart;
    cudaGetSymbolAddress((void**)&hq, g_hidden_q);
    cudaGetSymbolAddress((void**)&hk, g_hidden_k);
    cudaGetSymbolAddress((void**)&hb, g_hbuf);
    cudaGetSymbolAddress((void**)&pbq, g_bq);
    cudaGetSymbolAddress((void**)&pbk, g_bk);
    cudaGetSymbolAddress((void**)&pbcnt, g_bcnt);
    cudaGetSymbolAddress((void**)&pbstart, g_bstart);
    cudaGetSymbolAddress((void**)&pqcnt, g_qcnt);
    cudaGetSymbolAddress((void**)&pqstart, g_qstart);

    zero_kernel<<<(NN + 255) / 256, 256>>>();

    dim3 g1(HIDDEN / 128, (NN + 127) / 128);
    sgemm_kernel<<<g1, 256>>>(Q,   lap, Wq1, bq1, hq, NN, HIDDEN, DIN, 1, 1);
    sgemm_kernel<<<g1, 256>>>(Kin, lap, Wk1, bk1, hk, NN, HIDDEN, DIN, 1, 1);

    dim3 g2(NBUCKETS / 128, (NN + 127) / 128);
    sgemm_kernel<<<g2, 256>>>(hq, nullptr, Wq2, bq2, l_q, NN, NBUCKETS, HIDDEN, 0, 0);
    sgemm_kernel<<<g2, 256>>>(hk, nullptr, Wk2, bk2, l_k, NN, NBUCKETS, HIDDEN, 0, 0);

    int warp_grid = (NN * 32 + 255) / 256;
    argmax_kernel<<<warp_grid, 256>>>(l_q, pbq);
    argmax_kernel<<<warp_grid, 256>>>(l_k, pbk);

    count_kernel<<<(NE + 255) / 256, 256>>>(ei);
    scan1024_kernel<<<1, NBUCKETS>>>(pbcnt, pbstart);
    scan1024_kernel<<<1, NBUCKETS>>>(pqcnt, pqstart);
    scanN_kernel<<<1, 1024>>>();
    scatter_kernel<<<(NE + 255) / 256, 256>>>(ei);
    build_tiles_kernel<<<(NBUCKETS + 255) / 256, 256>>>();
    sortfilter_kernel<<<(NN + 255) / 256, 256>>>();

    attn_dense_kernel<<<MAXT, 512>>>(Q, Kin, V, lap, spdb, dse, dde, bnds, deg);

    dim3 g3(HIDDEN / 128, (NN + 127) / 128);
    sgemm_kernel<<<g3, 256>>>(hb, nullptr, Wout, bout, out, NN, HIDDEN, HIDDEN, 0, 0);
}

// round 3
// speedup vs baseline: 1.5938x; 1.0146x over previous
#include <cuda_runtime.h>
#include <math_constants.h>

#define NN 20000
#define HIDDEN 128
#define HEADS 8
#define LAP 16
#define NBUCKETS 1024
#define NBINS 32
#define MAXDEG 64
#define NE 320000
#define DIN (HIDDEN + LAP)
#define TQ 16
#define TK 32
#define MAXT 4096

// ---------------- device scratch (no allocations allowed) ----------------
__device__ float g_hidden_q[NN * HIDDEN];
__device__ float g_hidden_k[NN * HIDDEN];
__device__ float g_hbuf[NN * HIDDEN];
__device__ int g_bq[NN];
__device__ int g_bk[NN];
__device__ int g_bcnt[NBUCKETS];
__device__ int g_bstart[NBUCKETS + 1];
__device__ int g_bcur[NBUCKETS];
__device__ int g_bnodes[NN];
__device__ int g_qcnt[NBUCKETS];
__device__ int g_qstart[NBUCKETS + 1];
__device__ int g_qcur[NBUCKETS];
__device__ int g_qnodes[NN];
__device__ int g_scnt[NN];
__device__ int g_soff[NN + 1];
__device__ int g_scur[NN];
__device__ int g_extra[NN];
__device__ int g_edst[NE];
__device__ int g_tile_b[MAXT];
__device__ int g_tile_off[MAXT];
__device__ int g_ntiles;

// ---------------- tiled SGEMM 128x128x8, 8x8 register tile ----------------
// C = act(A@B + bias). A: MxK row-major (concat: A is MxHIDDEN, A2 MxLAP).
// Requires Nn % 128 == 0, K % 8 == 0 (144, 128 both OK).
__global__ __launch_bounds__(256) void sgemm_kernel(
    const float* __restrict__ A, const float* __restrict__ A2,
    const float* __restrict__ B, const float* __restrict__ bias,
    float* __restrict__ C, int M, int Nn, int K, int relu, int concat)
{
    const int BM = 128, BN = 128, BK = 8;
    __shared__ float As[BK][BM + 4];  // pad to 132 (16B-aligned rows)
    __shared__ float Bs[BK][BN];
    int t = threadIdx.x;
    int bm = blockIdx.y * BM, bn = blockIdx.x * BN;
    int tx = t & 15, ty = t >> 4;
    int arow = t >> 1, ak = (t & 1) * 4;    // A: 128 rows x 8 k, one float4/thread
    int bkr = t >> 5, bcol = (t & 31) * 4;  // B: 8 k x 128 cols
    float acc[8][8] = {};

    for (int kt = 0; kt < K; kt += BK) {
        int row = bm + arow;
        float4 av = make_float4(0.f, 0.f, 0.f, 0.f);
        if (row < M) {
            int k0 = kt + ak;
            if (!concat) {
                av = *(const float4*)(A + (size_t)row * K + k0);
            } else if (k0 < HIDDEN) {
                av = *(const float4*)(A + (size_t)row * HIDDEN + k0);
            } else {
                av = *(const float4*)(A2 + (size_t)row * LAP + (k0 - HIDDEN));
            }
        }
        As[ak + 0][arow] = av.x;
        As[ak + 1][arow] = av.y;
        As[ak + 2][arow] = av.z;
        As[ak + 3][arow] = av.w;
        *(float4*)&Bs[bkr][bcol] = *(const float4*)(B + (size_t)(kt + bkr) * Nn + bn + bcol);
        __syncthreads();
#pragma unroll
        for (int kk = 0; kk < BK; kk++) {
            float a[8], b[8];
            *(float4*)(a)     = *(const float4*)&As[kk][ty * 8];
            *(float4*)(a + 4) = *(const float4*)&As[kk][ty * 8 + 4];
            *(float4*)(b)     = *(const float4*)&Bs[kk][tx * 8];
            *(float4*)(b + 4) = *(const float4*)&Bs[kk][tx * 8 + 4];
#pragma unroll
            for (int i2 = 0; i2 < 8; i2++)
#pragma unroll
                for (int j2 = 0; j2 < 8; j2++)
                    acc[i2][j2] += a[i2] * b[j2];
        }
        __syncthreads();
    }
#pragma unroll
    for (int i2 = 0; i2 < 8; i2++) {
        int gm = bm + ty * 8 + i2;
        if (gm >= M) continue;
#pragma unroll
        for (int j2 = 0; j2 < 8; j2++) {
            int gn = bn + tx * 8 + j2;
            float v = acc[i2][j2] + bias[gn];
            if (relu) v = fmaxf(v, 0.f);
            C[(size_t)gm * Nn + gn] = v;
        }
    }
}

// ---------------- argmax over 1024 buckets, one warp per row ----------------
__global__ void argmax_kernel(const float* __restrict__ L, int* __restrict__ outb)
{
    int w = (blockIdx.x * blockDim.x + threadIdx.x) >> 5;
    int lane = threadIdx.x & 31;
    if (w >= NN) return;
    const float* row = L + (size_t)w * NBUCKETS;
    float best = -CUDART_INF_F;
    int bidx = 0;
#pragma unroll 4
    for (int t2 = 0; t2 < NBUCKETS / 32; t2++) {
        int idx = t2 * 32 + lane;
        float v = row[idx];
        if (v > best) { best = v; bidx = idx; }
    }
    for (int o = 16; o; o >>= 1) {
        float v2 = __shfl_xor_sync(~0u, best, o);
        int i2 = __shfl_xor_sync(~0u, bidx, o);
        if (v2 > best || (v2 == best && i2 < bidx)) { best = v2; bidx = i2; }
    }
    if (lane == 0) outb[w] = bidx;
}

// ---------------- bucket grouping / edge CSR ----------------
__global__ void zero_kernel()
{
    int i = blockIdx.x * blockDim.x + threadIdx.x;
    if (i < NBUCKETS) { g_bcnt[i] = 0; g_bcur[i] = 0; g_qcnt[i] = 0; g_qcur[i] = 0; }
    if (i < NN) { g_scnt[i] = 0; g_scur[i] = 0; }
    if (i == 0) g_ntiles = 0;
}

__global__ void count_kernel(const int* __restrict__ ei)
{
    int i = blockIdx.x * blockDim.x + threadIdx.x;
    if (i < NN) {
        atomicAdd(&g_bcnt[g_bk[i]], 1);
        atomicAdd(&g_qcnt[g_bq[i]], 1);
    }
    if (i < NE) atomicAdd(&g_scnt[ei[i]], 1);
}

__global__ void scan1024_kernel(const int* __restrict__ cnt, int* __restrict__ start)
{
    __shared__ int sh[NBUCKETS];
    int t = threadIdx.x;
    sh[t] = cnt[t];
    __syncthreads();
    for (int o = 1; o < NBUCKETS; o <<= 1) {
        int x = (t >= o) ? sh[t - o] : 0;
        __syncthreads();
        sh[t] += x;
        __syncthreads();
    }
    start[t + 1] = sh[t];
    if (t == 0) start[0] = 0;
}

__global__ void scanN_kernel()
{
    __shared__ int sh[1024];
    __shared__ int carry;
    int t = threadIdx.x;
    if (t == 0) { carry = 0; g_soff[0] = 0; }
    __syncthreads();
    for (int base = 0; base < NN; base += 1024) {
        int v = (base + t < NN) ? g_scnt[base + t] : 0;
        sh[t] = v;
        __syncthreads();
        for (int o = 1; o < 1024; o <<= 1) {
            int x = (t >= o) ? sh[t - o] : 0;
            __syncthreads();
            sh[t] += x;
            __syncthreads();
        }
        if (base + t < NN) g_soff[base + t + 1] = carry + sh[t];
        __syncthreads();
        if (t == 0) carry += sh[1023];
        __syncthreads();
    }
}

__global__ void scatter_kernel(const int* __restrict__ ei)
{
    int i = blockIdx.x * blockDim.x + threadIdx.x;
    if (i < NN) {
        int b = g_bk[i];
        int p = g_bstart[b] + atomicAdd(&g_bcur[b], 1);
        g_bnodes[p] = i;
        int qb = g_bq[i];
        int q = g_qstart[qb] + atomicAdd(&g_qcur[qb], 1);
        g_qnodes[q] = i;
    }
    if (i < NE) {
        int s = ei[i];
        int p = g_soff[s] + atomicAdd(&g_scur[s], 1);
        g_edst[p] = ei[NE + i];
    }
}

__global__ void build_tiles_kernel()
{
    int b = blockIdx.x * blockDim.x + threadIdx.x;
    if (b >= NBUCKETS) return;
    int nq = g_qstart[b + 1] - g_qstart[b];
    if (nq == 0) return;
    int nt = (nq + TQ - 1) / TQ;
    int pos = atomicAdd(&g_ntiles, nt);
    for (int k = 0; k < nt; k++) {
        g_tile_b[pos + k] = b;
        g_tile_off[pos + k] = k * TQ;
    }
}

// sort each src's dst list, drop duplicates and pairs already covered by the
// LSH set {j : bk[j]==bq[s], j!=s}; keep self-loops (LSH excludes i==j).
__global__ void sortfilter_kernel()
{
    int s = blockIdx.x * blockDim.x + threadIdx.x;
    if (s >= NN) return;
    int off = g_soff[s], cnt = g_soff[s + 1] - off;
    for (int a = 1; a < cnt; a++) {
        int key = g_edst[off + a];
        int b = a - 1;
        while (b >= 0 && g_edst[off + b] > key) {
            g_edst[off + b + 1] = g_edst[off + b];
            b--;
        }
        g_edst[off + b + 1] = key;
    }
    int myb = g_bq[s];
    int m2 = 0, prev = -1;
    for (int a = 0; a < cnt; a++) {
        int j = g_edst[off + a];
        if (j == prev) continue;
        prev = j;
        if (j != s && g_bk[j] == myb) continue;
        g_edst[off + m2++] = j;
    }
    g_extra[s] = m2;
}

// ---------------- bucket-dense attention, smem K/V tiles ----------------
// One block = TQ srcs of one bucket (one warp per src). Loops over the
// bucket's K-node list in TK tiles staged in shared memory.
__global__ __launch_bounds__(512) void attn_dense_kernel(
    const float* __restrict__ Q, const float* __restrict__ K,
    const float* __restrict__ V, const float* __restrict__ lap,
    const float* __restrict__ spd_bias,
    const float* __restrict__ dse_emb,
    const float* __restrict__ dde_emb,
    const float* __restrict__ bnds,
    const int* __restrict__ deg)
{
    __shared__ float4 Ks4[TK][32];
    __shared__ float4 Vs4[TK][32];
    __shared__ float laps_s[TK][16];
    __shared__ float dde_s[TK * HEADS];
    __shared__ float spd_s[(NBINS + 1) * HEADS];
    __shared__ int jid[TK];

    int t = blockIdx.x;
    if (t >= g_ntiles) return;
    int tid = threadIdx.x;
    int w = tid >> 5, lane = tid & 31;

    if (tid < (NBINS + 1) * HEADS) spd_s[tid] = spd_bias[tid];

    int b = g_tile_b[t], qo = g_tile_off[t];
    int q0 = g_qstart[b], nq = g_qstart[b + 1] - q0;
    int valid = (qo + w) < nq;
    int i = valid ? g_qnodes[q0 + qo + w] : 0;

    float4 q4 = *(const float4*)(Q + (size_t)i * HIDDEN + lane * 4);
    float pei = lap[i * LAP + (lane & 15)];
    float bnd = bnds[lane];
    int h = lane >> 2;
    int dsrc = min(max(deg[i], 0), MAXDEG + 1);
    float dse_h = dse_emb[dsrc * HEADS + h];

    float m = -CUDART_INF_F, dden = 0.f;
    float4 acc = make_float4(0.f, 0.f, 0.f, 0.f);

    int p0 = g_bstart[b], nk = g_bstart[b + 1] - p0;

    for (int kt = 0; kt < nk; kt += TK) {
        int cnt = min(TK, nk - kt);
        __syncthreads();   // protect previous iteration's smem reads
        if (tid < cnt) jid[tid] = g_bnodes[p0 + kt + tid];
        if (tid < cnt * HEADS) {
            int jj = tid >> 3;
            int j = g_bnodes[p0 + kt + jj];
            int dj = min(max(deg[j], 0), MAXDEG + 1);
            dde_s[tid] = dde_emb[dj * HEADS + (tid & 7)];
        }
        if (tid < cnt * LAP) {
            int jj = tid >> 4;
            int j = g_bnodes[p0 + kt + jj];
            laps_s[jj][tid & 15] = lap[j * LAP + (tid & 15)];
        }
        for (int x = tid; x < cnt * 32; x += 512) {
            int jj = x >> 5, l = x & 31;
            int j = g_bnodes[p0 + kt + jj];
            Ks4[jj][l] = ((const float4*)(K + (size_t)j * HIDDEN))[l];
            Vs4[jj][l] = ((const float4*)(V + (size_t)j * HIDDEN))[l];
        }
        __syncthreads();
        if (valid) {
            for (int jj = 0; jj < cnt; jj++) {
                int j = jid[jj];
                if (j == i) continue;   // warp-uniform
                float4 k4 = Ks4[jj][lane];
                float s = q4.x * k4.x + q4.y * k4.y + q4.z * k4.z + q4.w * k4.w;
                s += __shfl_xor_sync(~0u, s, 1);
                s += __shfl_xor_sync(~0u, s, 2);
                float dd = pei - laps_s[jj][lane & 15];
                float d2 = dd * dd;
                d2 += __shfl_xor_sync(~0u, d2, 1);
                d2 += __shfl_xor_sync(~0u, d2, 2);
                d2 += __shfl_xor_sync(~0u, d2, 4);
                d2 += __shfl_xor_sync(~0u, d2, 8);
                float dist = sqrtf(d2);
                unsigned bal = __ballot_sync(~0u, bnd < dist);
                int idx = __popc(bal);
                float sc = s * 0.25f + spd_s[idx * HEADS + h] + dse_h + dde_s[jj * HEADS + h];
                if (sc > m) {
                    float f = __expf(m - sc);
                    dden *= f;
                    acc.x *= f; acc.y *= f; acc.z *= f; acc.w *= f;
                    m = sc;
                }
                float wgt = __expf(sc - m);
                dden += wgt;
                float4 v4 = Vs4[jj][lane];
                acc.x += wgt * v4.x; acc.y += wgt * v4.y;
                acc.z += wgt * v4.z; acc.w += wgt * v4.w;
            }
        }
    }
    __syncthreads();   // spd_s safety when nk == 0

    if (valid) {
        // graph-edge extras (deduped, LSH-filtered) — global loads, few per src
        int eo = g_soff[i], ec = g_extra[i];
        for (int e = 0; e < ec; e++) {
            int j = g_edst[eo + e];
            float4 k4 = *(const float4*)(K + (size_t)j * HIDDEN + lane * 4);
            float s = q4.x * k4.x + q4.y * k4.y + q4.z * k4.z + q4.w * k4.w;
            s += __shfl_xor_sync(~0u, s, 1);
            s += __shfl_xor_sync(~0u, s, 2);
            float dd = pei - lap[j * LAP + (lane & 15)];
            float d2 = dd * dd;
            d2 += __shfl_xor_sync(~0u, d2, 1);
            d2 += __shfl_xor_sync(~0u, d2, 2);
            d2 += __shfl_xor_sync(~0u, d2, 4);
            d2 += __shfl_xor_sync(~0u, d2, 8);
            float dist = sqrtf(d2);
            unsigned bal = __ballot_sync(~0u, bnd < dist);
            int idx = __popc(bal);
            int dj = min(max(deg[j], 0), MAXDEG + 1);
            float sc = s * 0.25f + spd_s[idx * HEADS + h] + dse_h + dde_emb[dj * HEADS + h];
            if (sc > m) {
                float f = __expf(m - sc);
                dden *= f;
                acc.x *= f; acc.y *= f; acc.z *= f; acc.w *= f;
                m = sc;
            }
            float wgt = __expf(sc - m);
            dden += wgt;
            float4 v4 = *(const float4*)(V + (size_t)j * HIDDEN + lane * 4);
            acc.x += wgt * v4.x; acc.y += wgt * v4.y;
            acc.z += wgt * v4.z; acc.w += wgt * v4.w;
        }
        float inv = 1.f / (dden + 1e-16f);
        float4 o = make_float4(acc.x * inv, acc.y * inv, acc.z * inv, acc.w * inv);
        *(float4*)(g_hbuf + (size_t)i * HIDDEN + lane * 4) = o;
    }
}

// ---------------- launch ----------------
extern "C" void kernel_launch(void* const* d_in, const int* in_sizes, int n_in,
                              void* d_out, int out_size)
{
    const float* Q    = (const float*)d_in[0];
    const float* Kin  = (const float*)d_in[1];
    const float* V    = (const float*)d_in[2];
    const float* lap  = (const float*)d_in[3];
    const float* Wq1  = (const float*)d_in[4];
    const float* bq1  = (const float*)d_in[5];
    const float* Wq2  = (const float*)d_in[6];
    const float* bq2  = (const float*)d_in[7];
    const float* Wk1  = (const float*)d_in[8];
    const float* bk1  = (const float*)d_in[9];
    const float* Wk2  = (const float*)d_in[10];
    const float* bk2  = (const float*)d_in[11];
    const float* spdb = (const float*)d_in[12];
    const float* dse  = (const float*)d_in[13];
    const float* dde  = (const float*)d_in[14];
    const float* Wout = (const float*)d_in[15];
    const float* bout = (const float*)d_in[16];
    const float* bnds = (const float*)d_in[17];
    const int*   ei   = (const int*)d_in[18];
    const int*   deg  = (const int*)d_in[19];

    float* out = (float*)d_out;
    float* l_q = out + (size_t)NN * HIDDEN;
    float* l_k = l_q + (size_t)NN * NBUCKETS;

    float *hq, *hk, *hb;
    int *pbq, *pbk, *pbcnt, *pbstart, *pqcnt, *pqstart;
    cudaGetSymbolAddress((void**)&hq, g_hidden_q);
    cudaGetSymbolAddress((void**)&hk, g_hidden_k);
    cudaGetSymbolAddress((void**)&hb, g_hbuf);
    cudaGetSymbolAddress((void**)&pbq, g_bq);
    cudaGetSymbolAddress((void**)&pbk, g_bk);
    cudaGetSymbolAddress((void**)&pbcnt, g_bcnt);
    cudaGetSymbolAddress((void**)&pbstart, g_bstart);
    cudaGetSymbolAddress((void**)&pqcnt, g_qcnt);
    cudaGetSymbolAddress((void**)&pqstart, g_qstart);

    zero_kernel<<<(NN + 255) / 256, 256>>>();

    dim3 g1(HIDDEN / 128, (NN + 127) / 128);
    sgemm_kernel<<<g1, 256>>>(Q,   lap, Wq1, bq1, hq, NN, HIDDEN, DIN, 1, 1);
    sgemm_kernel<<<g1, 256>>>(Kin, lap, Wk1, bk1, hk, NN, HIDDEN, DIN, 1, 1);

    dim3 g2(NBUCKETS / 128, (NN + 127) / 128);
    sgemm_kernel<<<g2, 256>>>(hq, nullptr, Wq2, bq2, l_q, NN, NBUCKETS, HIDDEN, 0, 0);
    sgemm_kernel<<<g2, 256>>>(hk, nullptr, Wk2, bk2, l_k, NN, NBUCKETS, HIDDEN, 0, 0);

    int warp_grid = (NN * 32 + 255) / 256;
    argmax_kernel<<<warp_grid, 256>>>(l_q, pbq);
    argmax_kernel<<<warp_grid, 256>>>(l_k, pbk);

    count_kernel<<<(NE + 255) / 256, 256>>>(ei);
    scan1024_kernel<<<1, NBUCKETS>>>(pbcnt, pbstart);
    scan1024_kernel<<<1, NBUCKETS>>>(pqcnt, pqstart);
    scanN_kernel<<<1, 1024>>>();
    scatter_kernel<<<(NE + 255) / 256, 256>>>(ei);
    build_tiles_kernel<<<(NBUCKETS + 255) / 256, 256>>>();
    sortfilter_kernel<<<(NN + 255) / 256, 256>>>();

    attn_dense_kernel<<<MAXT, 512>>>(Q, Kin, V, lap, spdb, dse, dde, bnds, deg);

    dim3 g3(HIDDEN / 128, (NN + 127) / 128);
    sgemm_kernel<<<g3, 256>>>(hb, nullptr, Wout, bout, out, NN, HIDDEN, HIDDEN, 0, 0);
}